// round 11
// baseline (speedup 1.0000x reference)
#include <cuda_runtime.h>
#include <cuda_fp16.h>
#include <cstdint>
#include <cstring>

#define NTOK 3136
#define CCH  96
#define BB   128
#define KSB  208   // smem row stride in bytes (13*16 -> conflict-free ldmatrix)
#define OSW  104   // out-staging row stride in floats

// ---------------- smem layout (bytes) ----------------
#define SM_HH  0
#define SM_WC  256
#define SM_XH  768
#define SM_BH  (SM_XH + BB * KSB)          // 27392
#define SMEM_BYTES (BB * OSW * 4)          // 53248 (> 47360 phase-A need)

__device__ __forceinline__ uint32_t smem_u32(const void* p) {
    uint32_t a;
    asm("{ .reg .u64 t; cvta.to.shared.u64 t, %1; cvt.u32.u64 %0, t; }"
        : "=r"(a) : "l"(p));
    return a;
}
__device__ __forceinline__ uint32_t h2_as_u32(__half2 h) {
    uint32_t u;
    memcpy(&u, &h, 4);
    return u;
}
__device__ __forceinline__ void ldsm_x4(uint32_t* r, uint32_t addr) {
    asm volatile("ldmatrix.sync.aligned.m8n8.x4.shared.b16 {%0,%1,%2,%3}, [%4];"
                 : "=r"(r[0]), "=r"(r[1]), "=r"(r[2]), "=r"(r[3]) : "r"(addr));
}
__device__ __forceinline__ void mma_fp16(float* c, const uint32_t* a,
                                         uint32_t b0, uint32_t b1) {
    asm volatile(
        "mma.sync.aligned.m16n8k16.row.col.f32.f16.f16.f32 "
        "{%0,%1,%2,%3}, {%4,%5,%6,%7}, {%8,%9}, {%0,%1,%2,%3};"
        : "+f"(c[0]), "+f"(c[1]), "+f"(c[2]), "+f"(c[3])
        : "r"(a[0]), "r"(a[1]), "r"(a[2]), "r"(a[3]), "r"(b0), "r"(b1));
}

// ---------------------------------------------------------------------------
// Fused kernel, warp-specialized prologue:
//   warps 0-3: w load -> DFT -> circulant B build (named barrier 1)
//   warps 4-7: stage X -> fp16 smem (concurrent)
// Then all 8 warps: Y[128,96] = X_fp16 * B^T via mma, staged epilogue.
// ---------------------------------------------------------------------------
extern __shared__ unsigned char smem_raw[];

__global__ void __launch_bounds__(256, 4)
gf_fused_kernel(const float* __restrict__ x, const float* __restrict__ w,
                float* __restrict__ out) {
    const int tid = threadIdx.x;
    const int n   = blockIdx.x;
    const size_t NC   = (size_t)NTOK * CCH;
    const size_t xoff = (size_t)n * CCH;

    if (tid < 128) {
        // ---- group A: w load -> DFT -> B build ----
        if (tid < 98)
            ((float*)(smem_raw + SM_WC))[tid] = w[(size_t)n * 98 + tid];
        asm volatile("bar.sync 1, 128;" ::: "memory");

        if (tid < CCH) {
            const float* wp = (const float*)(smem_raw + SM_WC);
            const int d = tid;
            float c1, s1;
            __sincosf((float)d * (6.283185307179586f / 96.0f), &s1, &c1);
            float acc = wp[0] + ((d & 1) ? -wp[96] : wp[96]);
            float c = c1, s = s1;
            float sum = 0.0f;
#pragma unroll 4
            for (int k = 1; k < 48; k++) {
                sum = fmaf(wp[2 * k], c, sum);
                sum = fmaf(-wp[2 * k + 1], s, sum);
                float cn = fmaf(c, c1, -s * s1);
                float sn = fmaf(s, c1,  c * s1);
                c = cn; s = sn;
            }
            float hv = (acc + 2.0f * sum) * (1.0f / 96.0f);
            ((unsigned short*)(smem_raw + SM_HH))[d] =
                __half_as_ushort(__float2half_rn(hv));
        }
        asm volatile("bar.sync 1, 128;" ::: "memory");

        // B build: row = tid (0..95); pair p -> (h[m], h[m-1]), m=(row-2p) mod 96
        if (tid < CCH) {
            const unsigned short* hh = (const unsigned short*)(smem_raw + SM_HH);
            const int row = tid;
            unsigned char* bp = smem_raw + SM_BH + (uint32_t)(row * KSB);
            int m = row;
#pragma unroll
            for (int p2 = 0; p2 < 24; p2++) {
                int m1 = m - 1; if (m1 < 0) m1 += CCH;
                int m2 = m1 - 1; if (m2 < 0) m2 += CCH;
                int m3 = m2 - 1; if (m3 < 0) m3 += CCH;
                uint2 v;
                v.x = (uint32_t)hh[m]  | ((uint32_t)hh[m1] << 16);
                v.y = (uint32_t)hh[m2] | ((uint32_t)hh[m3] << 16);
                *(uint2*)(bp + p2 * 8) = v;
                m = m3 - 1; if (m < 0) m += CCH;
            }
        }
    } else {
        // ---- group B: stage X -> fp16 smem (12 chunks/thread) ----
        const int t = tid - 128;
#pragma unroll
        for (int it = 0; it < 12; it++) {
            int idx = t + it * 128;              // 0..1535
            int row = idx / 12, c8 = idx % 12;
            const float4* src = (const float4*)(x + (size_t)row * NC + xoff + (size_t)(c8 * 8));
            float4 v0 = src[0];
            float4 v1 = src[1];
            uint4 o;
            o.x = h2_as_u32(__floats2half2_rn(v0.x, v0.y));
            o.y = h2_as_u32(__floats2half2_rn(v0.z, v0.w));
            o.z = h2_as_u32(__floats2half2_rn(v1.x, v1.y));
            o.w = h2_as_u32(__floats2half2_rn(v1.z, v1.w));
            *(uint4*)(smem_raw + SM_XH + (uint32_t)(row * KSB + c8 * 16)) = o;
        }
    }
    __syncthreads();

    // ---- MMA: warp = 32 rows x 48 cols ----
    const int wid  = tid >> 5;
    const int lane = tid & 31;
    const int m0   = (wid & 3) * 32;
    const int n0   = (wid >> 2) * 48;

    const uint32_t base  = smem_u32(smem_raw);
    const int lrow  = lane & 15;
    const int lhalf = (lane >> 4) << 4;

    const uint32_t a_b = base + SM_XH + (uint32_t)((m0 + lrow) * KSB) + lhalf;
    const uint32_t b_b = base + SM_BH + (uint32_t)((n0 + lrow) * KSB) + lhalf;

    float acc[2][6][4];
#pragma unroll
    for (int mh = 0; mh < 2; mh++)
#pragma unroll
        for (int nt = 0; nt < 6; nt++)
#pragma unroll
            for (int q = 0; q < 4; q++) acc[mh][nt][q] = 0.0f;

#pragma unroll
    for (int ks = 0; ks < 6; ks++) {
        const uint32_t koff = (uint32_t)(ks * 32);
        uint32_t b0[4], b1[4], b2[4], a0[4], a1[4];
        ldsm_x4(b0, b_b + koff);
        ldsm_x4(b1, b_b + koff + 16 * KSB);
        ldsm_x4(b2, b_b + koff + 32 * KSB);
        ldsm_x4(a0, a_b + koff);
        ldsm_x4(a1, a_b + koff + 16 * KSB);
        mma_fp16(acc[0][0], a0, b0[0], b0[2]);
        mma_fp16(acc[0][1], a0, b0[1], b0[3]);
        mma_fp16(acc[0][2], a0, b1[0], b1[2]);
        mma_fp16(acc[0][3], a0, b1[1], b1[3]);
        mma_fp16(acc[0][4], a0, b2[0], b2[2]);
        mma_fp16(acc[0][5], a0, b2[1], b2[3]);
        mma_fp16(acc[1][0], a1, b0[0], b0[2]);
        mma_fp16(acc[1][1], a1, b0[1], b0[3]);
        mma_fp16(acc[1][2], a1, b1[0], b1[2]);
        mma_fp16(acc[1][3], a1, b1[1], b1[3]);
        mma_fp16(acc[1][4], a1, b2[0], b2[2]);
        mma_fp16(acc[1][5], a1, b2[1], b2[3]);
    }

    // ---- staged epilogue ----
    __syncthreads();
    {
        float* stg = (float*)smem_raw;
        const int rb = m0 + (lane >> 2);
        const int cb = n0 + (lane & 3) * 2;
#pragma unroll
        for (int mh = 0; mh < 2; mh++) {
            const int r0 = rb + mh * 16;
#pragma unroll
            for (int nt = 0; nt < 6; nt++) {
                const int col = cb + nt * 8;
                *(float2*)(stg + r0 * OSW + col)       = make_float2(acc[mh][nt][0], acc[mh][nt][1]);
                *(float2*)(stg + (r0 + 8) * OSW + col) = make_float2(acc[mh][nt][2], acc[mh][nt][3]);
            }
        }
    }
    __syncthreads();
    {
        const float* stg = (const float*)smem_raw;
#pragma unroll
        for (int i = 0; i < 12; i++) {
            int g   = tid + i * 256;          // 0..3071
            int row = g / 24, c4 = (g % 24) * 4;
            float4 v = *(const float4*)(stg + row * OSW + c4);
            *(float4*)(out + (size_t)row * NC + xoff + c4) = v;
        }
    }
}

// ---------------------------------------------------------------------------
extern "C" void kernel_launch(void* const* d_in, const int* in_sizes, int n_in,
                              void* d_out, int out_size) {
    const float* x = (const float*)d_in[0];   // [B, N, C] f32
    const float* w = (const float*)d_in[1];   // [N, 49, 2] f32
    float* out = (float*)d_out;

    cudaFuncSetAttribute(gf_fused_kernel,
                         cudaFuncAttributeMaxDynamicSharedMemorySize, SMEM_BYTES);
    gf_fused_kernel<<<NTOK, 256, SMEM_BYTES>>>(x, w, out);
}

// round 12
// speedup vs baseline: 1.5478x; 1.5478x over previous
#include <cuda_runtime.h>
#include <cuda_fp16.h>
#include <cstdint>
#include <cstring>

#define NTOK 3136
#define CCH  96
#define BB   128
#define KSB  208   // smem row stride in bytes (13*16 -> conflict-free ldmatrix)
#define OSW  104   // out-staging row stride in floats

// ---------------- smem layout (bytes) ----------------
#define SM_HH  0
#define SM_WC  256
#define SM_XH  768
#define SM_BH  (SM_XH + BB * KSB)          // 27392
#define SMEM_BYTES (BB * OSW * 4)          // 53248 (> 47360 phase-A need)

__device__ __forceinline__ uint32_t smem_u32(const void* p) {
    uint32_t a;
    asm("{ .reg .u64 t; cvta.to.shared.u64 t, %1; cvt.u32.u64 %0, t; }"
        : "=r"(a) : "l"(p));
    return a;
}
__device__ __forceinline__ uint32_t h2_as_u32(__half2 h) {
    uint32_t u;
    memcpy(&u, &h, 4);
    return u;
}
__device__ __forceinline__ void ldsm_x4(uint32_t* r, uint32_t addr) {
    asm volatile("ldmatrix.sync.aligned.m8n8.x4.shared.b16 {%0,%1,%2,%3}, [%4];"
                 : "=r"(r[0]), "=r"(r[1]), "=r"(r[2]), "=r"(r[3]) : "r"(addr));
}
__device__ __forceinline__ void mma_fp16(float* c, const uint32_t* a,
                                         uint32_t b0, uint32_t b1) {
    asm volatile(
        "mma.sync.aligned.m16n8k16.row.col.f32.f16.f16.f32 "
        "{%0,%1,%2,%3}, {%4,%5,%6,%7}, {%8,%9}, {%0,%1,%2,%3};"
        : "+f"(c[0]), "+f"(c[1]), "+f"(c[2]), "+f"(c[3])
        : "r"(a[0]), "r"(a[1]), "r"(a[2]), "r"(a[3]), "r"(b0), "r"(b1));
}

// ---------------------------------------------------------------------------
// Fused kernel, warp-specialized prologue at 3 CTAs/SM:
//   warps 0-3: w load -> DFT -> circulant B build (named barrier 1)
//   warps 4-7: stage X -> fp16 smem (concurrent)
// Then all 8 warps: Y[128,96] = X_fp16 * B^T via mma, staged epilogue.
// ---------------------------------------------------------------------------
extern __shared__ unsigned char smem_raw[];

__global__ void __launch_bounds__(256, 3)
gf_fused_kernel(const float* __restrict__ x, const float* __restrict__ w,
                float* __restrict__ out) {
    const int tid = threadIdx.x;
    const int n   = blockIdx.x;
    const size_t NC   = (size_t)NTOK * CCH;
    const size_t xoff = (size_t)n * CCH;

    if (tid < 128) {
        // ---- group A: w load -> DFT -> B build ----
        if (tid < 98)
            ((float*)(smem_raw + SM_WC))[tid] = w[(size_t)n * 98 + tid];
        asm volatile("bar.sync 1, 128;" ::: "memory");

        if (tid < CCH) {
            const float* wp = (const float*)(smem_raw + SM_WC);
            const int d = tid;
            float c1, s1;
            __sincosf((float)d * (6.283185307179586f / 96.0f), &s1, &c1);
            float acc = wp[0] + ((d & 1) ? -wp[96] : wp[96]);
            float c = c1, s = s1;
            float sum = 0.0f;
#pragma unroll 4
            for (int k = 1; k < 48; k++) {
                sum = fmaf(wp[2 * k], c, sum);
                sum = fmaf(-wp[2 * k + 1], s, sum);
                float cn = fmaf(c, c1, -s * s1);
                float sn = fmaf(s, c1,  c * s1);
                c = cn; s = sn;
            }
            float hv = (acc + 2.0f * sum) * (1.0f / 96.0f);
            ((unsigned short*)(smem_raw + SM_HH))[d] =
                __half_as_ushort(__float2half_rn(hv));
        }
        asm volatile("bar.sync 1, 128;" ::: "memory");

        // B build: row = tid (0..95); pair p -> (h[m], h[m-1]), m=(row-2p) mod 96
        if (tid < CCH) {
            const unsigned short* hh = (const unsigned short*)(smem_raw + SM_HH);
            const int row = tid;
            unsigned char* bp = smem_raw + SM_BH + (uint32_t)(row * KSB);
            int m = row;
#pragma unroll
            for (int p2 = 0; p2 < 24; p2++) {
                int m1 = m - 1; if (m1 < 0) m1 += CCH;
                int m2 = m1 - 1; if (m2 < 0) m2 += CCH;
                int m3 = m2 - 1; if (m3 < 0) m3 += CCH;
                uint2 v;
                v.x = (uint32_t)hh[m]  | ((uint32_t)hh[m1] << 16);
                v.y = (uint32_t)hh[m2] | ((uint32_t)hh[m3] << 16);
                *(uint2*)(bp + p2 * 8) = v;
                m = m3 - 1; if (m < 0) m += CCH;
            }
        }
    } else {
        // ---- group B: stage X -> fp16 smem (12 chunks/thread) ----
        const int t = tid - 128;
#pragma unroll
        for (int it = 0; it < 12; it++) {
            int idx = t + it * 128;              // 0..1535
            int row = idx / 12, c8 = idx % 12;
            const float4* src = (const float4*)(x + (size_t)row * NC + xoff + (size_t)(c8 * 8));
            float4 v0 = src[0];
            float4 v1 = src[1];
            uint4 o;
            o.x = h2_as_u32(__floats2half2_rn(v0.x, v0.y));
            o.y = h2_as_u32(__floats2half2_rn(v0.z, v0.w));
            o.z = h2_as_u32(__floats2half2_rn(v1.x, v1.y));
            o.w = h2_as_u32(__floats2half2_rn(v1.z, v1.w));
            *(uint4*)(smem_raw + SM_XH + (uint32_t)(row * KSB + c8 * 16)) = o;
        }
    }
    __syncthreads();

    // ---- MMA: warp = 32 rows x 48 cols ----
    const int wid  = tid >> 5;
    const int lane = tid & 31;
    const int m0   = (wid & 3) * 32;
    const int n0   = (wid >> 2) * 48;

    const uint32_t base  = smem_u32(smem_raw);
    const int lrow  = lane & 15;
    const int lhalf = (lane >> 4) << 4;

    const uint32_t a_b = base + SM_XH + (uint32_t)((m0 + lrow) * KSB) + lhalf;
    const uint32_t b_b = base + SM_BH + (uint32_t)((n0 + lrow) * KSB) + lhalf;

    float acc[2][6][4];
#pragma unroll
    for (int mh = 0; mh < 2; mh++)
#pragma unroll
        for (int nt = 0; nt < 6; nt++)
#pragma unroll
            for (int q = 0; q < 4; q++) acc[mh][nt][q] = 0.0f;

#pragma unroll
    for (int ks = 0; ks < 6; ks++) {
        const uint32_t koff = (uint32_t)(ks * 32);
        uint32_t b0[4], b1[4], b2[4], a0[4], a1[4];
        ldsm_x4(b0, b_b + koff);
        ldsm_x4(b1, b_b + koff + 16 * KSB);
        ldsm_x4(b2, b_b + koff + 32 * KSB);
        ldsm_x4(a0, a_b + koff);
        ldsm_x4(a1, a_b + koff + 16 * KSB);
        mma_fp16(acc[0][0], a0, b0[0], b0[2]);
        mma_fp16(acc[0][1], a0, b0[1], b0[3]);
        mma_fp16(acc[0][2], a0, b1[0], b1[2]);
        mma_fp16(acc[0][3], a0, b1[1], b1[3]);
        mma_fp16(acc[0][4], a0, b2[0], b2[2]);
        mma_fp16(acc[0][5], a0, b2[1], b2[3]);
        mma_fp16(acc[1][0], a1, b0[0], b0[2]);
        mma_fp16(acc[1][1], a1, b0[1], b0[3]);
        mma_fp16(acc[1][2], a1, b1[0], b1[2]);
        mma_fp16(acc[1][3], a1, b1[1], b1[3]);
        mma_fp16(acc[1][4], a1, b2[0], b2[2]);
        mma_fp16(acc[1][5], a1, b2[1], b2[3]);
    }

    // ---- staged epilogue ----
    __syncthreads();
    {
        float* stg = (float*)smem_raw;
        const int rb = m0 + (lane >> 2);
        const int cb = n0 + (lane & 3) * 2;
#pragma unroll
        for (int mh = 0; mh < 2; mh++) {
            const int r0 = rb + mh * 16;
#pragma unroll
            for (int nt = 0; nt < 6; nt++) {
                const int col = cb + nt * 8;
                *(float2*)(stg + r0 * OSW + col)       = make_float2(acc[mh][nt][0], acc[mh][nt][1]);
                *(float2*)(stg + (r0 + 8) * OSW + col) = make_float2(acc[mh][nt][2], acc[mh][nt][3]);
            }
        }
    }
    __syncthreads();
    {
        const float* stg = (const float*)smem_raw;
#pragma unroll 3
        for (int i = 0; i < 12; i++) {
            int g   = tid + i * 256;          // 0..3071
            int row = g / 24, c4 = (g % 24) * 4;
            float4 v = *(const float4*)(stg + row * OSW + c4);
            *(float4*)(out + (size_t)row * NC + xoff + c4) = v;
        }
    }
}

// ---------------------------------------------------------------------------
extern "C" void kernel_launch(void* const* d_in, const int* in_sizes, int n_in,
                              void* d_out, int out_size) {
    const float* x = (const float*)d_in[0];   // [B, N, C] f32
    const float* w = (const float*)d_in[1];   // [N, 49, 2] f32
    float* out = (float*)d_out;

    cudaFuncSetAttribute(gf_fused_kernel,
                         cudaFuncAttributeMaxDynamicSharedMemorySize, SMEM_BYTES);
    gf_fused_kernel<<<NTOK, 256, SMEM_BYTES>>>(x, w, out);
}

// round 13
// speedup vs baseline: 1.6643x; 1.0752x over previous
#include <cuda_runtime.h>
#include <cuda_fp16.h>
#include <cstdint>
#include <cstring>

#define NTOK 3136
#define CCH  96
#define BB   128
#define KSB  208   // smem row stride in bytes (13*16 -> conflict-free ldmatrix)
#define OSW  104   // out-staging row stride in floats

// ---------------- smem layout (bytes) ----------------
// HE: 192 fp16 rev-dup (+2B spill into pad), HO: shifted copy, 17-bank offset
#define SM_HE  0                            // 384B + pad to 452
#define SM_HO  452                          // 384B, ends 836
#define SM_WC  960                          // 98 f32 -> ends 1352
#define SM_XH  1472                         // 128 x 208 B = 26624 -> ends 28096
#define SM_BH  28096                        // 96 x 208 B = 19968 -> ends 48064
#define SMEM_BYTES (BB * OSW * 4)           // 53248 (> 48064 phase-A need)

__device__ __forceinline__ uint32_t smem_u32(const void* p) {
    uint32_t a;
    asm("{ .reg .u64 t; cvta.to.shared.u64 t, %1; cvt.u32.u64 %0, t; }"
        : "=r"(a) : "l"(p));
    return a;
}
__device__ __forceinline__ uint32_t h2_as_u32(__half2 h) {
    uint32_t u;
    memcpy(&u, &h, 4);
    return u;
}
__device__ __forceinline__ void ldsm_x4(uint32_t* r, uint32_t addr) {
    asm volatile("ldmatrix.sync.aligned.m8n8.x4.shared.b16 {%0,%1,%2,%3}, [%4];"
                 : "=r"(r[0]), "=r"(r[1]), "=r"(r[2]), "=r"(r[3]) : "r"(addr));
}
__device__ __forceinline__ void mma_fp16(float* c, const uint32_t* a,
                                         uint32_t b0, uint32_t b1) {
    asm volatile(
        "mma.sync.aligned.m16n8k16.row.col.f32.f16.f16.f32 "
        "{%0,%1,%2,%3}, {%4,%5,%6,%7}, {%8,%9}, {%0,%1,%2,%3};"
        : "+f"(c[0]), "+f"(c[1]), "+f"(c[2]), "+f"(c[3])
        : "r"(a[0]), "r"(a[1]), "r"(a[2]), "r"(a[3]), "r"(b0), "r"(b1));
}

// ---------------------------------------------------------------------------
// Fused kernel, warp-specialized prologue at 3 CTAs/SM:
//   warps 0-3: w load -> DFT -> HE/HO rev arrays -> B rows via contiguous copy
//   warps 4-7: stage X -> fp16 smem, fully-coalesced LDG + conflict-free STS
// Then all 8 warps: Y[128,96] = X_fp16 * B^T via mma, staged epilogue.
// ---------------------------------------------------------------------------
extern __shared__ unsigned char smem_raw[];

__global__ void __launch_bounds__(256, 3)
gf_fused_kernel(const float* __restrict__ x, const float* __restrict__ w,
                float* __restrict__ out) {
    const int tid = threadIdx.x;
    const int n   = blockIdx.x;
    const size_t NC   = (size_t)NTOK * CCH;
    const size_t xoff = (size_t)n * CCH;

    if (tid < 128) {
        // ---- group A: w load -> DFT -> rev arrays -> B build ----
        if (tid < 98)
            ((float*)(smem_raw + SM_WC))[tid] = w[(size_t)n * 98 + tid];
        asm volatile("bar.sync 1, 128;" ::: "memory");

        if (tid < CCH) {
            const float* wp = (const float*)(smem_raw + SM_WC);
            const int d = tid;
            float c1, s1;
            __sincosf((float)d * (6.283185307179586f / 96.0f), &s1, &c1);
            float acc = wp[0] + ((d & 1) ? -wp[96] : wp[96]);
            float c = c1, s = s1;
            float sum = 0.0f;
#pragma unroll 4
            for (int k = 1; k < 48; k++) {
                sum = fmaf(wp[2 * k], c, sum);
                sum = fmaf(-wp[2 * k + 1], s, sum);
                float cn = fmaf(c, c1, -s * s1);
                float sn = fmaf(s, c1,  c * s1);
                c = cn; s = sn;
            }
            float hv = (acc + 2.0f * sum) * (1.0f / 96.0f);
            unsigned short hb = __half_as_ushort(__float2half_rn(hv));
            // HE[i] = h[(96-i) mod 96] (dup); HO[i] = h[(95-i) mod 96] (dup)
            unsigned short* HE = (unsigned short*)(smem_raw + SM_HE);
            unsigned short* HO = (unsigned short*)(smem_raw + SM_HO);
            const int i1 = 96 - d;          // 1..96
            HE[i1] = hb;
            HE[i1 + 96] = hb;               // index 192 (d=0) lands in pad
            HO[95 - d] = hb;
            HO[191 - d] = hb;
        }
        asm volatile("bar.sync 1, 128;" ::: "memory");

        // B row r = 48 contiguous u32 from HE (r even) / HO (r odd)
        if (tid < CCH) {
            const int r = tid;
            const uint32_t* sp = (r & 1)
                ? (const uint32_t*)(smem_raw + SM_HO) + ((95 - r) >> 1)
                : (const uint32_t*)(smem_raw + SM_HE) + ((96 - r) >> 1);
            uint4* dp = (uint4*)(smem_raw + SM_BH + (uint32_t)(r * KSB));
#pragma unroll
            for (int c = 0; c < 12; c++) {
                uint4 v;
                v.x = sp[4 * c + 0];
                v.y = sp[4 * c + 1];
                v.z = sp[4 * c + 2];
                v.w = sp[4 * c + 3];
                dp[c] = v;
            }
        }
    } else {
        // ---- group B: stage X, coalesced. 8 lanes cover one 128B row-chunk ----
        const int t  = tid - 128;
        const int w2 = t >> 5, l = t & 31;
        const int g  = l >> 3, k = l & 7;
        // lane-octet row offsets {0,4,1,5}; warp bases {0,2,8,10}
        const int row_base = ((w2 >> 1) << 3) + ((w2 & 1) << 1)
                           + ((g & 1) << 2) + (g >> 1);
#pragma unroll 4
        for (int p = 0; p < 8; p++) {
            const int row = (p << 4) + row_base;
            const float4* src = (const float4*)(x + (size_t)row * NC + xoff);
#pragma unroll
            for (int j = 0; j < 3; j++) {
                const int c16 = k + (j << 3);
                float4 v = src[c16];
                uint2 o;
                o.x = h2_as_u32(__floats2half2_rn(v.x, v.y));
                o.y = h2_as_u32(__floats2half2_rn(v.z, v.w));
                *(uint2*)(smem_raw + SM_XH + (uint32_t)(row * KSB + c16 * 8)) = o;
            }
        }
    }
    __syncthreads();

    // ---- MMA: warp = 32 rows x 48 cols ----
    const int wid  = tid >> 5;
    const int lane = tid & 31;
    const int m0   = (wid & 3) * 32;
    const int n0   = (wid >> 2) * 48;

    const uint32_t base  = smem_u32(smem_raw);
    const int lrow  = lane & 15;
    const int lhalf = (lane >> 4) << 4;

    const uint32_t a_b = base + SM_XH + (uint32_t)((m0 + lrow) * KSB) + lhalf;
    const uint32_t b_b = base + SM_BH + (uint32_t)((n0 + lrow) * KSB) + lhalf;

    float acc[2][6][4];
#pragma unroll
    for (int mh = 0; mh < 2; mh++)
#pragma unroll
        for (int nt = 0; nt < 6; nt++)
#pragma unroll
            for (int q = 0; q < 4; q++) acc[mh][nt][q] = 0.0f;

#pragma unroll
    for (int ks = 0; ks < 6; ks++) {
        const uint32_t koff = (uint32_t)(ks * 32);
        uint32_t b0[4], b1[4], b2[4], a0[4], a1[4];
        ldsm_x4(b0, b_b + koff);
        ldsm_x4(b1, b_b + koff + 16 * KSB);
        ldsm_x4(b2, b_b + koff + 32 * KSB);
        ldsm_x4(a0, a_b + koff);
        ldsm_x4(a1, a_b + koff + 16 * KSB);
        mma_fp16(acc[0][0], a0, b0[0], b0[2]);
        mma_fp16(acc[0][1], a0, b0[1], b0[3]);
        mma_fp16(acc[0][2], a0, b1[0], b1[2]);
        mma_fp16(acc[0][3], a0, b1[1], b1[3]);
        mma_fp16(acc[0][4], a0, b2[0], b2[2]);
        mma_fp16(acc[0][5], a0, b2[1], b2[3]);
        mma_fp16(acc[1][0], a1, b0[0], b0[2]);
        mma_fp16(acc[1][1], a1, b0[1], b0[3]);
        mma_fp16(acc[1][2], a1, b1[0], b1[2]);
        mma_fp16(acc[1][3], a1, b1[1], b1[3]);
        mma_fp16(acc[1][4], a1, b2[0], b2[2]);
        mma_fp16(acc[1][5], a1, b2[1], b2[3]);
    }

    // ---- staged epilogue ----
    __syncthreads();
    {
        float* stg = (float*)smem_raw;
        const int rb = m0 + (lane >> 2);
        const int cb = n0 + (lane & 3) * 2;
#pragma unroll
        for (int mh = 0; mh < 2; mh++) {
            const int r0 = rb + mh * 16;
#pragma unroll
            for (int nt = 0; nt < 6; nt++) {
                const int col = cb + nt * 8;
                *(float2*)(stg + r0 * OSW + col)       = make_float2(acc[mh][nt][0], acc[mh][nt][1]);
                *(float2*)(stg + (r0 + 8) * OSW + col) = make_float2(acc[mh][nt][2], acc[mh][nt][3]);
            }
        }
    }
    __syncthreads();
    {
        const float* stg = (const float*)smem_raw;
#pragma unroll 3
        for (int i = 0; i < 12; i++) {
            int g2  = tid + i * 256;          // 0..3071
            int row = g2 / 24, c4 = (g2 % 24) * 4;
            float4 v = *(const float4*)(stg + row * OSW + c4);
            *(float4*)(out + (size_t)row * NC + xoff + c4) = v;
        }
    }
}

// ---------------------------------------------------------------------------
extern "C" void kernel_launch(void* const* d_in, const int* in_sizes, int n_in,
                              void* d_out, int out_size) {
    const float* x = (const float*)d_in[0];   // [B, N, C] f32
    const float* w = (const float*)d_in[1];   // [N, 49, 2] f32
    float* out = (float*)d_out;

    cudaFuncSetAttribute(gf_fused_kernel,
                         cudaFuncAttributeMaxDynamicSharedMemorySize, SMEM_BYTES);
    gf_fused_kernel<<<NTOK, 256, SMEM_BYTES>>>(x, w, out);
}